// round 4
// baseline (speedup 1.0000x reference)
#include <cuda_runtime.h>
#include <math.h>

#define NINST 128
#define CT_   80
#define CS_   53
#define H_    400
#define W_    400
#define HW_   (H_ * W_)
#define MS_   28
#define NCH   (CS_ + NINST)      // 181
#define HG_   1600
#define THREADS 64
#define PXT   4
#define GRID_ (HW_ / (THREADS * PXT))   // 625

static_assert(HW_ % (THREADS * PXT) == 0, "exact grid");
static_assert(W_ % PXT == 0, "float4 group never crosses a row");

struct InstQ {
    int   ylo, xlo;             // bilinear/box origin (>=0)
    int   y2m, x2m;             // mask-valid upper bound inclusive
    int   cy2, cx2;             // semantic box exclusive upper
    float scy, scx;             // MS / hh, MS / ww
    int   thing_off;            // cls * HW
    int   mask_off;             // (n*CT + cls) * MS*MS
};

__device__ float g_nll[GRID_];
__device__ int   g_cnt[GRID_];
__device__ int   g_done = 0;

__global__ void __launch_bounds__(THREADS)
pan_fused_kernel(const float* __restrict__ mask_logits,
                 const float* __restrict__ stuff_logit,
                 const float* __restrict__ thing_logit,
                 const float* __restrict__ bbox,
                 const int*   __restrict__ cls_idx,
                 const int*   __restrict__ gt,
                 float* __restrict__ out, int out_size)
{
    __shared__ ushort4 sbox[NINST];      // ylo, yhi, xlo, xhi (union box)
    __shared__ InstQ   sq[NINST];
    __shared__ float   warp_s[THREADS / 32];
    __shared__ int     warp_c[THREADS / 32];
    __shared__ int     s_last;

    const int tid = threadIdx.x;

    // ---- per-block instance parameter setup ----
    for (int n = tid; n < NINST; n += THREADS) {
        float x0f = bbox[n * 4 + 0];
        float y0f = bbox[n * 4 + 1];
        float x2f = bbox[n * 4 + 2];
        float y2f = bbox[n * 4 + 3];
        int cls = cls_idx[n];

        int x0b = (int)floorf(x0f * 0.25f);
        int y0b = (int)floorf(y0f * 0.25f);
        int x2b = (int)floorf(x2f * 0.25f);
        int y2b = (int)floorf(y2f * 0.25f);
        int hh = y2b - y0b + 1;
        int ww = x2b - x0b + 1;

        int cx2 = (int)(rintf(x2f * 0.25f) + 1.0f);
        int cy2 = (int)(rintf(y2f * 0.25f) + 1.0f);

        InstQ q;
        q.ylo = max(y0b, 0);
        q.xlo = max(x0b, 0);
        q.y2m = min(y2b, H_ - 1);
        q.x2m = min(x2b, W_ - 1);
        q.cy2 = cy2;
        q.cx2 = cx2;
        q.scy = (float)MS_ / (float)hh;
        q.scx = (float)MS_ / (float)ww;
        q.thing_off = cls * HW_;
        q.mask_off  = (n * CT_ + cls) * (MS_ * MS_);
        sq[n] = q;

        int yhi = min(max(y2b, cy2 - 1), H_ - 1);
        int xhi = min(max(x2b, cx2 - 1), W_ - 1);
        sbox[n] = make_ushort4((unsigned short)q.ylo, (unsigned short)yhi,
                               (unsigned short)q.xlo, (unsigned short)xhi);
    }
    __syncthreads();

    const int p0 = (blockIdx.x * THREADS + tid) * PXT;
    const int y  = p0 / W_;            // all 4 pixels share this row
    const int x0 = p0 - y * W_;

    // downsampled GT: gt[4y, 4x]
    int gv[PXT];
    {
        const int gbase = (y * 4) * HG_ + x0 * 4;
        #pragma unroll
        for (int j = 0; j < PXT; ++j) gv[j] = gt[gbase + j * 4];
    }

    float s[PXT] = {0.f, 0.f, 0.f, 0.f};

    // ---- stuff channels: copy + exp (float4 streaming) ----
    #pragma unroll 2
    for (int c = 0; c < CS_; ++c) {
        float4 v = *reinterpret_cast<const float4*>(stuff_logit + c * HW_ + p0);
        *reinterpret_cast<float4*>(out + c * HW_ + p0) = v;
        s[0] += __expf(v.x);
        s[1] += __expf(v.y);
        s[2] += __expf(v.z);
        s[3] += __expf(v.w);
    }

    // ---- thing channels ----
    int nzero = 0;
    const float4 zero4 = make_float4(0.f, 0.f, 0.f, 0.f);
    for (int n = 0; n < NINST; ++n) {
        ushort4 b = sbox[n];
        if (y >= (int)b.x && y <= (int)b.y &&
            x0 + (PXT - 1) >= (int)b.z && x0 <= (int)b.w) {
            InstQ q = sq[n];

            // semantic logit fetch (one float4, gated by y/x feasibility)
            float tvr[PXT] = {0.f, 0.f, 0.f, 0.f};
            const bool ysem = (y < q.cy2);
            if (ysem && x0 < q.cx2) {
                float4 tv = *reinterpret_cast<const float4*>(
                    thing_logit + q.thing_off + p0);
                tvr[0] = tv.x; tvr[1] = tv.y; tvr[2] = tv.z; tvr[3] = tv.w;
            }

            // row bilinear setup (y uniform per thread)
            float sy = ((float)(y - q.ylo) + 0.5f) * q.scy - 0.5f;
            float fy = floorf(sy);
            float ty = sy - fy;
            int iyi = (int)fy;
            int iy0 = min(max(iyi, 0), MS_ - 1);
            int iy1 = min(max(iyi + 1, 0), MS_ - 1);
            const float* __restrict__ r0 = mask_logits + q.mask_off + iy0 * MS_;
            const float* __restrict__ r1 = mask_logits + q.mask_off + iy1 * MS_;
            const bool yrow = (y <= q.y2m);
            const float omty = 1.0f - ty;

            float v[PXT];
            #pragma unroll
            for (int j = 0; j < PXT; ++j) {
                int px = x0 + j;
                bool inx = (px >= q.xlo);
                float val = (ysem && inx && px < q.cx2) ? tvr[j] : 0.0f;
                if (yrow && inx && px <= q.x2m) {
                    float sx = ((float)(px - q.xlo) + 0.5f) * q.scx - 0.5f;
                    float fx = floorf(sx);
                    float tx = sx - fx;
                    int ixi = (int)fx;
                    int ix0 = min(max(ixi, 0), MS_ - 1);
                    int ix1 = min(max(ixi + 1, 0), MS_ - 1);
                    float c0 = r0[ix0] * omty + r1[ix0] * ty;
                    float c1 = r0[ix1] * omty + r1[ix1] * ty;
                    val += c0 * (1.0f - tx) + c1 * tx;
                }
                v[j] = val;
                s[j] += __expf(val);   // exp(0)==1 exactly for uncovered px
            }
            *reinterpret_cast<float4*>(out + (CS_ + n) * HW_ + p0) =
                make_float4(v[0], v[1], v[2], v[3]);
        } else {
            nzero++;
            *reinterpret_cast<float4*>(out + (CS_ + n) * HW_ + p0) = zero4;
        }
    }

    // ---- per-pixel NLL (target logit via same-thread readback) ----
    float nll_t = 0.0f;
    int   cnt_t = 0;
    #pragma unroll
    for (int j = 0; j < PXT; ++j) {
        float sj = s[j] + (float)nzero;
        int   gg = gv[j];
        int   tgt = min(max(gg, 0), NCH - 1);
        float vt = out[tgt * HW_ + p0 + j];   // same thread wrote it
        if (gg != 255) {
            nll_t += __logf(sj) - vt;
            cnt_t += 1;
        }
    }

    // ---- deterministic intra-block reduction (shfl butterfly) ----
    #pragma unroll
    for (int off = 16; off > 0; off >>= 1) {
        nll_t += __shfl_xor_sync(0xffffffffu, nll_t, off);
        cnt_t += __shfl_xor_sync(0xffffffffu, cnt_t, off);
    }
    const int wid = tid >> 5;
    const int lid = tid & 31;
    if (lid == 0) { warp_s[wid] = nll_t; warp_c[wid] = cnt_t; }
    __syncthreads();
    if (tid == 0) {
        float bs = 0.f; int bc = 0;
        #pragma unroll
        for (int w = 0; w < THREADS / 32; ++w) { bs += warp_s[w]; bc += warp_c[w]; }
        g_nll[blockIdx.x] = bs;
        g_cnt[blockIdx.x] = bc;
        __threadfence();
        int t = atomicAdd(&g_done, 1);
        s_last = (t == GRID_ - 1) ? 1 : 0;
    }
    __syncthreads();

    // ---- last block folds the final loss reduce (fixed order -> deterministic) ----
    if (s_last) {
        float fs = 0.f; int fc = 0;
        for (int i = tid; i < GRID_; i += THREADS) {   // fixed order per thread
            fs += __ldcg(&g_nll[i]);
            fc += __ldcg(&g_cnt[i]);
        }
        #pragma unroll
        for (int off = 16; off > 0; off >>= 1) {
            fs += __shfl_xor_sync(0xffffffffu, fs, off);
            fc += __shfl_xor_sync(0xffffffffu, fc, off);
        }
        if (lid == 0) { warp_s[wid] = fs; warp_c[wid] = fc; }
        __syncthreads();
        if (tid == 0) {
            float ts = 0.f; int tc = 0;
            #pragma unroll
            for (int w = 0; w < THREADS / 32; ++w) { ts += warp_s[w]; tc += warp_c[w]; }
            out[out_size - 1] = ts / fmaxf((float)tc, 1.0f);  // LOSS_W = 1.0
            g_done = 0;   // reset for next graph replay
        }
    }
}

extern "C" void kernel_launch(void* const* d_in, const int* in_sizes, int n_in,
                              void* d_out, int out_size)
{
    const float* mask_logits = (const float*)d_in[0];
    const float* stuff_logit = (const float*)d_in[1];
    const float* thing_logit = (const float*)d_in[2];
    const float* bbox        = (const float*)d_in[3];
    const int*   cls_idx     = (const int*)d_in[4];
    const int*   gt          = (const int*)d_in[5];
    float* out = (float*)d_out;

    pan_fused_kernel<<<GRID_, THREADS>>>(mask_logits, stuff_logit, thing_logit,
                                         bbox, cls_idx, gt, out, out_size);
}

// round 6
// speedup vs baseline: 1.2679x; 1.2679x over previous
#include <cuda_runtime.h>
#include <math.h>

#define NINST 128
#define CT_   80
#define CS_   53
#define H_    400
#define W_    400
#define HW_   (H_ * W_)
#define MS_   28
#define NCH   (CS_ + NINST)      // 181
#define HG_   1600
#define THREADS 128
#define PXT   2
#define BLKPX (THREADS * PXT)           // 256 px per block
#define GRID_ (HW_ / BLKPX)             // 625

static_assert(HW_ % BLKPX == 0, "exact grid");
static_assert(W_ % PXT == 0, "pixel pair never crosses a row");
static_assert(NINST == THREADS, "one instance per thread in setup pass");

struct InstQ {
    int   ylo, xlo;             // bilinear/box origin (>=0)
    int   y2m, x2m;             // mask-valid upper bound inclusive
    int   cy2, cx2;             // semantic box exclusive upper
    float scy, scx;             // MS / hh, MS / ww
    int   thing_off;            // cls * HW
    int   mask_off;             // (n*CT + cls) * MS*MS
};

__device__ float g_nll[GRID_];
__device__ int   g_cnt[GRID_];
__device__ int   g_done = 0;

__global__ void __launch_bounds__(THREADS)
pan_fused_kernel(const float* __restrict__ mask_logits,
                 const float* __restrict__ stuff_logit,
                 const float* __restrict__ thing_logit,
                 const float* __restrict__ bbox,
                 const int*   __restrict__ cls_idx,
                 const int*   __restrict__ gt,
                 float* __restrict__ out, int out_size)
{
    __shared__ ushort4 sbox[NINST];          // ylo, yhi, xlo, xhi (union box)
    __shared__ InstQ   sq[NINST];
    __shared__ unsigned char sflag[NINST];
    __shared__ short   clist[NINST];         // candidates (instance order)
    __shared__ short   zlist[NINST];         // complement (instance order)
    __shared__ int     s_ncand, s_nz;
    __shared__ float   warp_s[THREADS / 32];
    __shared__ int     warp_c[THREADS / 32];
    __shared__ int     s_last;

    const int tid    = threadIdx.x;
    const int p0base = blockIdx.x * BLKPX;
    const int bymin  = p0base / W_;
    const int bymax  = (p0base + BLKPX - 1) / W_;
    // x-range of this block's pixels (full row range if the block spans 2 rows)
    const int bxlo = (bymin == bymax) ? (p0base - bymin * W_) : 0;
    const int bxhi = (bymin == bymax) ? (bxlo + BLKPX - 1)    : (W_ - 1);

    // ---- per-block instance setup: one instance per thread ----
    {
        const int n = tid;
        float x0f = bbox[n * 4 + 0];
        float y0f = bbox[n * 4 + 1];
        float x2f = bbox[n * 4 + 2];
        float y2f = bbox[n * 4 + 3];
        int cls = cls_idx[n];

        int x0b = (int)floorf(x0f * 0.25f);
        int y0b = (int)floorf(y0f * 0.25f);
        int x2b = (int)floorf(x2f * 0.25f);
        int y2b = (int)floorf(y2f * 0.25f);
        int hh = y2b - y0b + 1;
        int ww = x2b - x0b + 1;

        int cx2 = (int)(rintf(x2f * 0.25f) + 1.0f);
        int cy2 = (int)(rintf(y2f * 0.25f) + 1.0f);

        InstQ q;
        q.ylo = max(y0b, 0);
        q.xlo = max(x0b, 0);
        q.y2m = min(y2b, H_ - 1);
        q.x2m = min(x2b, W_ - 1);
        q.cy2 = cy2;
        q.cx2 = cx2;
        q.scy = (float)MS_ / (float)hh;
        q.scx = (float)MS_ / (float)ww;
        q.thing_off = cls * HW_;
        q.mask_off  = (n * CT_ + cls) * (MS_ * MS_);
        sq[n] = q;

        int yhi = min(max(y2b, cy2 - 1), H_ - 1);
        int xhi = min(max(x2b, cx2 - 1), W_ - 1);
        sbox[n] = make_ushort4((unsigned short)q.ylo, (unsigned short)yhi,
                               (unsigned short)q.xlo, (unsigned short)xhi);
        // candidate iff union box intersects this block's pixel region
        sflag[n] = (yhi >= bymin && q.ylo <= bymax &&
                    xhi >= bxlo  && q.xlo <= bxhi) ? 1 : 0;
    }
    __syncthreads();

    // ---- deterministic compaction (instance order) by thread 0 ----
    if (tid == 0) {
        int m = 0, z = 0;
        #pragma unroll 4
        for (int n = 0; n < NINST; ++n) {
            if (sflag[n]) clist[m++] = (short)n;
            else          zlist[z++] = (short)n;
        }
        s_ncand = m;
        s_nz    = z;
    }
    __syncthreads();
    const int ncand = s_ncand;
    const int nz    = s_nz;

    const int p0 = p0base + tid * PXT;
    const int y  = p0 / W_;
    const int x0 = p0 - y * W_;

    // downsampled GT: gt[4y, 4x]
    int gv[PXT];
    {
        const int gbase = (y * 4) * HG_ + x0 * 4;
        #pragma unroll
        for (int j = 0; j < PXT; ++j) gv[j] = gt[gbase + j * 4];
    }

    float s0 = 0.f, s1 = 0.f;

    // ---- stuff channels: copy + exp (float2 streaming) ----
    #pragma unroll 4
    for (int c = 0; c < CS_; ++c) {
        float2 v = *reinterpret_cast<const float2*>(stuff_logit + c * HW_ + p0);
        *reinterpret_cast<float2*>(out + c * HW_ + p0) = v;
        s0 += __expf(v.x);
        s1 += __expf(v.y);
    }

    // ---- non-candidate thing channels: pure zero-store stream ----
    const float2 zero2 = make_float2(0.f, 0.f);
    #pragma unroll 4
    for (int i = 0; i < nz; ++i) {
        int n = (int)zlist[i];
        *reinterpret_cast<float2*>(out + (CS_ + n) * HW_ + p0) = zero2;
    }

    // ---- candidate thing channels ----
    int cov0 = 0, cov1 = 0;     // count of exp'd (covered) channels per pixel
    for (int i = 0; i < ncand; ++i) {
        int n = (int)clist[i];
        ushort4 b = sbox[n];
        bool in0 = (y >= (int)b.x && y <= (int)b.y &&
                    x0     >= (int)b.z && x0     <= (int)b.w);
        bool in1 = (y >= (int)b.x && y <= (int)b.y &&
                    x0 + 1 >= (int)b.z && x0 + 1 <= (int)b.w);
        float v0 = 0.f, v1 = 0.f;
        if (in0 | in1) {
            InstQ q = sq[n];

            // semantic logit (float2 gated fetch)
            float t0 = 0.f, t1 = 0.f;
            const bool ysem = (y < q.cy2);
            if (ysem && x0 < q.cx2) {
                float2 tv = *reinterpret_cast<const float2*>(
                    thing_logit + q.thing_off + p0);
                t0 = tv.x; t1 = tv.y;
            }

            // row bilinear setup (y uniform)
            float sy = ((float)(y - q.ylo) + 0.5f) * q.scy - 0.5f;
            float fy = floorf(sy);
            float ty = sy - fy;
            int iyi = (int)fy;
            int iy0 = min(max(iyi, 0), MS_ - 1);
            int iy1 = min(max(iyi + 1, 0), MS_ - 1);
            const float* __restrict__ r0 = mask_logits + q.mask_off + iy0 * MS_;
            const float* __restrict__ r1 = mask_logits + q.mask_off + iy1 * MS_;
            const bool yrow = (y <= q.y2m);
            const float omty = 1.0f - ty;

            #pragma unroll
            for (int j = 0; j < PXT; ++j) {
                bool inj = (j == 0) ? in0 : in1;
                if (!inj) continue;
                int px = x0 + j;
                float val = (ysem && px < q.cx2) ? ((j == 0) ? t0 : t1) : 0.0f;
                if (yrow && px >= q.xlo && px <= q.x2m) {
                    float sx = ((float)(px - q.xlo) + 0.5f) * q.scx - 0.5f;
                    float fx = floorf(sx);
                    float tx = sx - fx;
                    int ixi = (int)fx;
                    int ix0 = min(max(ixi, 0), MS_ - 1);
                    int ix1 = min(max(ixi + 1, 0), MS_ - 1);
                    float c0 = r0[ix0] * omty + r1[ix0] * ty;
                    float c1 = r0[ix1] * omty + r1[ix1] * ty;
                    val += c0 * (1.0f - tx) + c1 * tx;
                }
                if (j == 0) { v0 = val; s0 += __expf(val); cov0++; }
                else        { v1 = val; s1 += __expf(val); cov1++; }
            }
        }
        *reinterpret_cast<float2*>(out + (CS_ + n) * HW_ + p0) =
            make_float2(v0, v1);
    }
    // uncovered thing channels contribute exp(0) == 1 each
    s0 += (float)(NINST - cov0);
    s1 += (float)(NINST - cov1);

    // ---- per-pixel NLL (target logit via same-thread readback) ----
    float nll_t = 0.0f;
    int   cnt_t = 0;
    {
        float ss[PXT] = { s0, s1 };
        #pragma unroll
        for (int j = 0; j < PXT; ++j) {
            int gg  = gv[j];
            int tgt = min(max(gg, 0), NCH - 1);
            float vt = out[tgt * HW_ + p0 + j];   // same thread wrote it
            if (gg != 255) {
                nll_t += __logf(ss[j]) - vt;
                cnt_t += 1;
            }
        }
    }

    // ---- deterministic intra-block reduction ----
    #pragma unroll
    for (int off = 16; off > 0; off >>= 1) {
        nll_t += __shfl_xor_sync(0xffffffffu, nll_t, off);
        cnt_t += __shfl_xor_sync(0xffffffffu, cnt_t, off);
    }
    const int wid = tid >> 5;
    const int lid = tid & 31;
    if (lid == 0) { warp_s[wid] = nll_t; warp_c[wid] = cnt_t; }
    __syncthreads();
    if (tid == 0) {
        float bs = 0.f; int bc = 0;
        #pragma unroll
        for (int w = 0; w < THREADS / 32; ++w) { bs += warp_s[w]; bc += warp_c[w]; }
        g_nll[blockIdx.x] = bs;
        g_cnt[blockIdx.x] = bc;
        __threadfence();
        int t = atomicAdd(&g_done, 1);
        s_last = (t == GRID_ - 1) ? 1 : 0;
    }
    __syncthreads();

    // ---- last block folds the final loss reduce (fixed order) ----
    if (s_last) {
        float fs = 0.f; int fc = 0;
        for (int i = tid; i < GRID_; i += THREADS) {
            fs += __ldcg(&g_nll[i]);
            fc += __ldcg(&g_cnt[i]);
        }
        #pragma unroll
        for (int off = 16; off > 0; off >>= 1) {
            fs += __shfl_xor_sync(0xffffffffu, fs, off);
            fc += __shfl_xor_sync(0xffffffffu, fc, off);
        }
        if (lid == 0) { warp_s[wid] = fs; warp_c[wid] = fc; }
        __syncthreads();
        if (tid == 0) {
            float ts = 0.f; int tc = 0;
            #pragma unroll
            for (int w = 0; w < THREADS / 32; ++w) { ts += warp_s[w]; tc += warp_c[w]; }
            out[out_size - 1] = ts / fmaxf((float)tc, 1.0f);  // LOSS_W = 1.0
            g_done = 0;   // reset for next graph replay
        }
    }
}

extern "C" void kernel_launch(void* const* d_in, const int* in_sizes, int n_in,
                              void* d_out, int out_size)
{
    const float* mask_logits = (const float*)d_in[0];
    const float* stuff_logit = (const float*)d_in[1];
    const float* thing_logit = (const float*)d_in[2];
    const float* bbox        = (const float*)d_in[3];
    const int*   cls_idx     = (const int*)d_in[4];
    const int*   gt          = (const int*)d_in[5];
    float* out = (float*)d_out;

    pan_fused_kernel<<<GRID_, THREADS>>>(mask_logits, stuff_logit, thing_logit,
                                         bbox, cls_idx, gt, out, out_size);
}